// round 14
// baseline (speedup 1.0000x reference)
#include <cuda_runtime.h>

// LambdaRankLoss N=8192, 5 integer classes (0..4), SIGMA=1.
//
//   e = exp(p), g = 2^t, d = 1/log2(rank+1), rank = stable ascending-by-target.
//   lambda_i = scale * ( e_i * T1_i - T2_i ),  scale = 1/maxDCG
//   T1_i = sum_c (G_c - g_i) * sum_{j in c} (d_i - d_j) r_ij,  r = 1/(e_i+e_j)
//   T2_i = sum_{c < v_i} (G_c - g_i)(n_c d_i - SD_c)     [O(1)]
//
// CLASS-ALIGNED PADDING (pad e=1e18 finite): each 128-j tile single-class ->
// static trip counts. RCP-MERGE: rp=rcp(s0*s1) serves both rows (1 MUFU/2 pairs).
// FUSED FINISH: per row-group arrival counter; the last pair block for a row
// group reduces all 70 slices, applies T2 + scale, writes out. No reduce kernel.

#define N      8192
#define K_DCG  512
#define NT     70            // 128-wide class-aligned j tiles
#define NPAD   (NT * 128)    // 8960
#define RBLK   256
#define NRB    (NPAD / RBLK) // 35
#define PAIR_T 128
#define PBLK   32
#define PADE   1.0e18f

__device__ float2 g_sed[NPAD];       // padded-sorted (e, -decay); pad = (1e18, 0)
__device__ int    g_inv[NPAD];       // padded pos -> original index; pad = -1
__device__ int    g_seg[8];          // TRUE class segment bounds
__device__ int    g_pbase[8];        // PADDED class segment bases
__device__ float  g_tGc[NT];         // per-tile class gain 2^c; 0.0 = all-pad tile
__device__ int    g_wpre[256][8];    // per-32-chunk exclusive prefix
__device__ float  g_pSD[PBLK][5];
__device__ float  g_pDCG[PBLK];
__device__ int    g_cnt[NRB];        // arrival counters (reset in prep_cscan)
__device__ float2 g_part[NT][NPAD / 2];

__device__ __forceinline__ float frcp(float x) {
    float r;
    asm("rcp.approx.f32 %0, %1;" : "=f"(r) : "f"(x));
    return r;
}

// ---------------- prep A: fused count + scan (single block, alu-only) ------
__global__ void __launch_bounds__(256)
prep_cscan(const float* __restrict__ tgt) {
    __shared__ int s[5][256];
    __shared__ int s_base[6];

    const int t = threadIdx.x;

    const float2 padval = make_float2(PADE, 0.0f);
    for (int i = t; i < NPAD; i += 256) {
        g_sed[i] = padval;
        g_inv[i] = -1;
    }
    if (t < NRB) g_cnt[t] = 0;                    // reset arrival counters

    int loc[5] = {0, 0, 0, 0, 0};
    const float4* __restrict__ tp = (const float4*)(tgt + t * 32);
    #pragma unroll
    for (int k = 0; k < 8; k++) {
        float4 v4 = __ldg(tp + k);
        int c0 = max(0, min(4, (int)v4.x));
        int c1 = max(0, min(4, (int)v4.y));
        int c2 = max(0, min(4, (int)v4.z));
        int c3 = max(0, min(4, (int)v4.w));
        loc[c0]++; loc[c1]++; loc[c2]++; loc[c3]++;
    }
    int own[5];
    #pragma unroll
    for (int c = 0; c < 5; c++) { own[c] = loc[c]; s[c][t] = loc[c]; }
    __syncthreads();

    for (int ofs = 1; ofs < 256; ofs <<= 1) {
        int a[5] = {0, 0, 0, 0, 0};
        if (t >= ofs) {
            #pragma unroll
            for (int c = 0; c < 5; c++) a[c] = s[c][t - ofs];
        }
        __syncthreads();
        #pragma unroll
        for (int c = 0; c < 5; c++) s[c][t] += a[c];
        __syncthreads();
    }

    if (t == 0) {
        int run = 0, prun = 0;
        int pb[6];
        #pragma unroll
        for (int c = 0; c < 5; c++) {
            int nc = s[c][255];
            s_base[c]  = run;
            g_seg[c]   = run;
            pb[c]      = prun;
            g_pbase[c] = prun;
            run  += nc;
            prun += ((nc + 127) / 128) * 128;
        }
        g_seg[5]   = N;
        pb[5]      = prun;
        g_pbase[5] = prun;
        for (int tl = 0; tl < NT; tl++) {
            int start = tl * 128;
            float gc = 0.0f;                      // 0 = all-pad tile (skipped)
            #pragma unroll
            for (int c = 0; c < 5; c++)
                if (start >= pb[c] && start < pb[c + 1]) gc = (float)(1 << c);
            g_tGc[tl] = gc;
        }
    }
    __syncthreads();

    #pragma unroll
    for (int c = 0; c < 5; c++)
        g_wpre[t][c] = s_base[c] + s[c][t] - own[c];       // exclusive (true pos)
}

// ---------------- prep B: scatter to PADDED sorted order + SD/DCG ----------
__global__ void __launch_bounds__(256)
prep_scatter(const float* __restrict__ pred, const float* __restrict__ tgt) {
    __shared__ float s_sd[8][5];
    __shared__ float s_dcg[8];

    const int i    = blockIdx.x * 256 + threadIdx.x;
    const int lane = threadIdx.x & 31;
    const int wid  = threadIdx.x >> 5;
    const int gw   = i >> 5;

    int v = (int)tgt[i];
    v = max(0, min(4, v));

    int intra = 0;
    #pragma unroll
    for (int c = 0; c < 5; c++) {
        unsigned b = __ballot_sync(0xffffffffu, v == c);
        if (v == c) intra = __popc(b & ((1u << lane) - 1u));
    }
    const int k  = g_wpre[gw][v] + intra;                  // TRUE sorted pos
    const int kp = g_pbase[v] + (k - g_seg[v]);            // PADDED pos

    const float e = __expf(pred[i]);
    const float d = __fdividef(1.0f, log2f((float)k + 2.0f));
    g_sed[kp] = make_float2(e, -d);
    g_inv[kp] = i;

    float term = 0.0f;
    if (k >= N - K_DCG) {
        int r = N - k;                                     // descending rank
        term = (exp2f((float)v) - 1.0f) / log2f((float)r + 1.0f);
    }

    #pragma unroll
    for (int c = 0; c < 5; c++) {
        float x = (v == c) ? d : 0.0f;
        #pragma unroll
        for (int o = 16; o > 0; o >>= 1)
            x += __shfl_down_sync(0xffffffffu, x, o);
        if (lane == 0) s_sd[wid][c] = x;
    }
    {
        float x = term;
        #pragma unroll
        for (int o = 16; o > 0; o >>= 1)
            x += __shfl_down_sync(0xffffffffu, x, o);
        if (lane == 0) s_dcg[wid] = x;
    }
    __syncthreads();

    if (threadIdx.x < 5) {
        float s = 0.0f;
        #pragma unroll
        for (int w = 0; w < 8; w++) s += s_sd[w][threadIdx.x];
        g_pSD[blockIdx.x][threadIdx.x] = s;
    } else if (threadIdx.x == 5) {
        float s = 0.0f;
        #pragma unroll
        for (int w = 0; w < 8; w++) s += s_dcg[w];
        g_pDCG[blockIdx.x] = s;
    }
}

// ---------------- pairwise + fused finish: grid (NRB, NT) ------------------
__global__ void __launch_bounds__(PAIR_T)
pair_kernel(float* __restrict__ out) {
    __shared__ bool  s_last;
    __shared__ float s_scale;
    __shared__ float s_SD[5];

    const int t  = threadIdx.x;
    const int r0 = blockIdx.x * RBLK + 2 * t;
    const int r1 = r0 + 1;

    const int pb1 = g_pbase[1], pb2 = g_pbase[2],
              pb3 = g_pbase[3], pb4 = g_pbase[4];

    const float2 a0 = g_sed[r0];
    const float2 a1 = g_sed[r1];
    const float e0 = a0.x, d0 = -a0.y;
    const float e1 = a1.x, d1 = -a1.y;
    const float gi0 = (float)(1 << ((r0 >= pb1) + (r0 >= pb2) + (r0 >= pb3) + (r0 >= pb4)));
    const float gi1 = (float)(1 << ((r1 >= pb1) + (r1 >= pb2) + (r1 >= pb3) + (r1 >= pb4)));

    const float Gc    = g_tGc[blockIdx.y];
    const float coef0 = Gc - gi0;
    const float coef1 = Gc - gi1;

    float2 res = make_float2(0.0f, 0.0f);

    bool skip = (Gc == 0.0f) ||
                __all_sync(0xffffffffu, (coef0 == 0.0f) && (coef1 == 0.0f));
    if (!skip) {
        const float4* __restrict__ p = (const float4*)(g_sed + blockIdx.y * 128);

        float A0a = 0.f, A0b = 0.f, A1a = 0.f, A1b = 0.f;

        #pragma unroll 8
        for (int j = 0; j < 64; j++) {
            const float4 w = __ldg(p + j);         // (e_a, nd_a, e_b, nd_b)
            {
                float s0  = e0 + w.x;
                float s1  = e1 + w.x;
                float rp  = frcp(s0 * s1);          // one MUFU for both rows
                float dd0 = d0 + w.y;
                float dd1 = d1 + w.y;
                A0a = fmaf(dd0, rp * s1, A0a);
                A1a = fmaf(dd1, rp * s0, A1a);
            }
            {
                float s0  = e0 + w.z;
                float s1  = e1 + w.z;
                float rp  = frcp(s0 * s1);
                float dd0 = d0 + w.w;
                float dd1 = d1 + w.w;
                A0b = fmaf(dd0, rp * s1, A0b);
                A1b = fmaf(dd1, rp * s0, A1b);
            }
        }
        res.x = coef0 * (A0a + A0b);
        res.y = coef1 * (A1a + A1b);
    }

    g_part[blockIdx.y][blockIdx.x * (RBLK / 2) + t] = res;

    // ---- arrival protocol: last block of this row group finishes it ----
    __syncthreads();                               // all stores issued
    if (t == 0) {
        __threadfence();                           // release our slice
        int old = atomicAdd(&g_cnt[blockIdx.x], 1);
        s_last = (old == NT - 1);
    }
    __syncthreads();
    if (!s_last) return;
    __threadfence();                               // acquire all slices

    // scale & SD from per-block partials (cheap, redundant per row group)
    const int lane = t & 31;
    const int wid  = t >> 5;
    if (wid == 0) {
        float x = g_pDCG[lane];                    // PBLK == 32
        #pragma unroll
        for (int o = 16; o > 0; o >>= 1)
            x += __shfl_down_sync(0xffffffffu, x, o);
        if (lane == 0) s_scale = __fdividef(1.0f, x);
    } else if (wid == 1) {
        #pragma unroll
        for (int c = 0; c < 5; c++) {
            float x = g_pSD[lane][c];
            #pragma unroll
            for (int o = 16; o > 0; o >>= 1)
                x += __shfl_down_sync(0xffffffffu, x, o);
            if (lane == 0) s_SD[c] = x;
        }
    }
    __syncthreads();

    // reduce 70 slices for 256 positions: 2 per thread (coalesced)
    const int base = blockIdx.x * RBLK;
    const int kpA  = base + t;
    const int kpB  = base + 128 + t;

    float T1a = 0.0f, T1b = 0.0f;
    #pragma unroll
    for (int s = 0; s < NT; s++) {
        const float* __restrict__ ps = (const float*)g_part[s];
        T1a += ps[kpA];
        T1b += ps[kpB];
    }

    #pragma unroll
    for (int h = 0; h < 2; h++) {
        const int   kp = h ? kpB : kpA;
        const float T1 = h ? T1b : T1a;
        const int  idx = g_inv[kp];
        if (idx < 0) continue;                     // padding slot

        const int v = (kp >= pb1) + (kp >= pb2) + (kp >= pb3) + (kp >= pb4);
        const float2 a = g_sed[kp];
        const float e = a.x;
        const float d = -a.y;
        const float g = (float)(1 << v);

        float T2 = 0.0f;
        #pragma unroll
        for (int c = 0; c < 4; c++) {
            if (c < v) {
                float nc = (float)(g_seg[c + 1] - g_seg[c]);
                T2 += ((float)(1 << c) - g) * (nc * d - s_SD[c]);
            }
        }
        out[idx] = s_scale * (e * T1 - T2);
    }
}

extern "C" void kernel_launch(void* const* d_in, const int* in_sizes, int n_in,
                              void* d_out, int out_size) {
    const float* pred = (const float*)d_in[0];
    const float* tgt  = (const float*)d_in[1];
    float* out        = (float*)d_out;

    prep_cscan<<<1, 256>>>(tgt);
    prep_scatter<<<PBLK, 256>>>(pred, tgt);
    dim3 grid(NRB, NT);
    pair_kernel<<<grid, PAIR_T>>>(out);
}

// round 15
// speedup vs baseline: 1.2321x; 1.2321x over previous
#include <cuda_runtime.h>

// LambdaRankLoss N=8192, 5 integer classes (0..4), SIGMA=1.
//
//   e = exp(p), g = 2^t, d = 1/log2(rank+1), rank = stable ascending-by-target.
//   lambda_i = scale * ( e_i * T1_i - T2_i ),  scale = 1/maxDCG
//   T1_i = sum_c (G_c - g_i) * sum_{j in c} (d_i - d_j) r_ij,  r = 1/(e_i+e_j)
//   T2_i = sum_{c < v_i} (G_c - g_i)(n_c d_i - SD_c)     [O(1), reduce]
//
// CLASS-ALIGNED PADDING (pad e=1e18 finite): each 128-j tile single-class ->
// static trip counts. RCP-MERGE: rp=rcp(s0*s1) serves both rows (1 MUFU/2 pairs).
// Fully multi-block prep: per-block counts, then scatter blocks derive all
// prefixes locally (shfl scans) -- no single-block scan kernel.

#define N      8192
#define K_DCG  512
#define NT     70            // 128-wide class-aligned j tiles
#define NPAD   (NT * 128)    // 8960
#define RBLK   256
#define NRB    (NPAD / RBLK) // 35
#define PAIR_T 128
#define PBLK   32
#define PADE   1.0e18f

__device__ float2 g_sed[NPAD];       // padded-sorted (e, -decay); pad = (1e18, 0)
__device__ int    g_inv[NPAD];       // padded pos -> original index; pad = -1
__device__ int    g_seg[8];          // TRUE class segment bounds
__device__ int    g_pbase[8];        // PADDED class segment bases
__device__ float  g_tGc[NT];         // per-tile class gain 2^c; 0.0 = all-pad tile
__device__ int    g_bcnt[PBLK][5];   // per-block class counts
__device__ float  g_pSD[PBLK][5];
__device__ float  g_pDCG[PBLK];
__device__ float2 g_part[NT][NPAD / 2];

__device__ __forceinline__ float frcp(float x) {
    float r;
    asm("rcp.approx.f32 %0, %1;" : "=f"(r) : "f"(x));
    return r;
}

// ---------------- prep 1: parallel clear + per-block class counts ----------
__global__ void __launch_bounds__(256)
prep_count(const float* __restrict__ tgt) {
    __shared__ int s_w[8][5];

    const int i    = blockIdx.x * 256 + threadIdx.x;
    const int lane = threadIdx.x & 31;
    const int wid  = threadIdx.x >> 5;

    const float2 padval = make_float2(PADE, 0.0f);
    g_sed[i] = padval;
    g_inv[i] = -1;
    if (i < NPAD - N) {
        g_sed[N + i] = padval;
        g_inv[N + i] = -1;
    }

    int v = (int)tgt[i];
    v = max(0, min(4, v));
    #pragma unroll
    for (int c = 0; c < 5; c++) {
        unsigned b = __ballot_sync(0xffffffffu, v == c);
        if (lane == c) s_w[wid][c] = __popc(b);
    }
    __syncthreads();

    if (threadIdx.x < 5) {
        int s = 0;
        #pragma unroll
        for (int w = 0; w < 8; w++) s += s_w[w][threadIdx.x];
        g_bcnt[blockIdx.x][threadIdx.x] = s;
    }
}

// ---------------- prep 2: local prefixes + scatter + SD/DCG + tables -------
__global__ void __launch_bounds__(256)
prep_scatter(const float* __restrict__ pred, const float* __restrict__ tgt) {
    __shared__ int   s_w[8][5];      // per-warp counts (this block)
    __shared__ int   s_gexc[5];      // global exclusive prefix of this block
    __shared__ int   s_tot[5];       // global class totals
    __shared__ float s_sd[8][5];
    __shared__ float s_dcg[8];

    const int i    = blockIdx.x * 256 + threadIdx.x;
    const int lane = threadIdx.x & 31;
    const int wid  = threadIdx.x >> 5;

    int v = (int)tgt[i];
    v = max(0, min(4, v));

    // per-warp counts + intra-warp stable rank
    int intra = 0;
    #pragma unroll
    for (int c = 0; c < 5; c++) {
        unsigned b = __ballot_sync(0xffffffffu, v == c);
        if (v == c) intra = __popc(b & ((1u << lane) - 1u));
        if (lane == c) s_w[wid][c] = __popc(b);
    }

    // warp 0: shfl scan over the 32 block totals, per class
    if (wid == 0) {
        #pragma unroll
        for (int c = 0; c < 5; c++) {
            int own = g_bcnt[lane][c];
            int x = own;
            #pragma unroll
            for (int o = 1; o < 32; o <<= 1) {
                int y = __shfl_up_sync(0xffffffffu, x, o);
                if (lane >= o) x += y;
            }
            if (lane == blockIdx.x) s_gexc[c] = x - own;
            if (lane == 31)         s_tot[c]  = x;
        }
    }
    __syncthreads();

    // derived tables in registers (all threads, cheap)
    int tot[5], baseT[5], pbase[6];
    {
        int run = 0, prun = 0;
        #pragma unroll
        for (int c = 0; c < 5; c++) {
            tot[c]   = s_tot[c];
            baseT[c] = run;
            pbase[c] = prun;
            run  += tot[c];
            prun += ((tot[c] + 127) >> 7) << 7;
        }
        pbase[5] = prun;
    }

    // in-block prefix over warps < wid for own class
    int wpre = 0;
    for (int w = 0; w < wid; w++) wpre += s_w[w][v];

    const int k  = baseT[v] + s_gexc[v] + wpre + intra;    // TRUE sorted pos
    const int kp = pbase[v] + (k - baseT[v]);              // PADDED pos

    const float e = __expf(pred[i]);
    const float d = __fdividef(1.0f, log2f((float)k + 2.0f));
    g_sed[kp] = make_float2(e, -d);
    g_inv[kp] = i;

    float term = 0.0f;
    if (k >= N - K_DCG) {
        int r = N - k;                                     // descending rank
        term = (exp2f((float)v) - 1.0f) / log2f((float)r + 1.0f);
    }

    // SD / DCG block partials
    #pragma unroll
    for (int c = 0; c < 5; c++) {
        float x = (v == c) ? d : 0.0f;
        #pragma unroll
        for (int o = 16; o > 0; o >>= 1)
            x += __shfl_down_sync(0xffffffffu, x, o);
        if (lane == 0) s_sd[wid][c] = x;
    }
    {
        float x = term;
        #pragma unroll
        for (int o = 16; o > 0; o >>= 1)
            x += __shfl_down_sync(0xffffffffu, x, o);
        if (lane == 0) s_dcg[wid] = x;
    }
    __syncthreads();

    if (threadIdx.x < 5) {
        float s = 0.0f;
        #pragma unroll
        for (int w = 0; w < 8; w++) s += s_sd[w][threadIdx.x];
        g_pSD[blockIdx.x][threadIdx.x] = s;
    } else if (threadIdx.x == 5) {
        float s = 0.0f;
        #pragma unroll
        for (int w = 0; w < 8; w++) s += s_dcg[w];
        g_pDCG[blockIdx.x] = s;
    }

    // block 0 publishes tables for pair/reduce kernels
    if (blockIdx.x == 0 && threadIdx.x == 0) {
        #pragma unroll
        for (int c = 0; c < 5; c++) { g_seg[c] = baseT[c]; g_pbase[c] = pbase[c]; }
        g_seg[5]   = N;
        g_pbase[5] = pbase[5];
        for (int tl = 0; tl < NT; tl++) {
            int start = tl * 128;
            float gc = 0.0f;                      // 0 = all-pad tile (skipped)
            #pragma unroll
            for (int c = 0; c < 5; c++)
                if (start >= pbase[c] && start < pbase[c] +
                    (((tot[c] + 127) >> 7) << 7)) gc = (float)(1 << c);
            g_tGc[tl] = gc;
        }
    }
}

// ---------------- pairwise: grid (NRB, NT); static 128-trip loop -----------
__global__ void __launch_bounds__(PAIR_T)
pair_kernel() {
    const int t  = threadIdx.x;
    const int r0 = blockIdx.x * RBLK + 2 * t;
    const int r1 = r0 + 1;

    const int pb1 = g_pbase[1], pb2 = g_pbase[2],
              pb3 = g_pbase[3], pb4 = g_pbase[4];

    const float2 a0 = g_sed[r0];
    const float2 a1 = g_sed[r1];
    const float e0 = a0.x, d0 = -a0.y;
    const float e1 = a1.x, d1 = -a1.y;
    const float gi0 = (float)(1 << ((r0 >= pb1) + (r0 >= pb2) + (r0 >= pb3) + (r0 >= pb4)));
    const float gi1 = (float)(1 << ((r1 >= pb1) + (r1 >= pb2) + (r1 >= pb3) + (r1 >= pb4)));

    const float Gc    = g_tGc[blockIdx.y];
    const float coef0 = Gc - gi0;
    const float coef1 = Gc - gi1;

    float2 res = make_float2(0.0f, 0.0f);

    bool skip = (Gc == 0.0f) ||
                __all_sync(0xffffffffu, (coef0 == 0.0f) && (coef1 == 0.0f));
    if (!skip) {
        const float4* __restrict__ p = (const float4*)(g_sed + blockIdx.y * 128);

        float A0a = 0.f, A0b = 0.f, A1a = 0.f, A1b = 0.f;

        #pragma unroll 8
        for (int j = 0; j < 64; j++) {
            const float4 w = __ldg(p + j);         // (e_a, nd_a, e_b, nd_b)
            {
                float s0  = e0 + w.x;
                float s1  = e1 + w.x;
                float rp  = frcp(s0 * s1);          // one MUFU for both rows
                float dd0 = d0 + w.y;
                float dd1 = d1 + w.y;
                A0a = fmaf(dd0, rp * s1, A0a);
                A1a = fmaf(dd1, rp * s0, A1a);
            }
            {
                float s0  = e0 + w.z;
                float s1  = e1 + w.z;
                float rp  = frcp(s0 * s1);
                float dd0 = d0 + w.w;
                float dd1 = d1 + w.w;
                A0b = fmaf(dd0, rp * s1, A0b);
                A1b = fmaf(dd1, rp * s0, A1b);
            }
        }
        res.x = coef0 * (A0a + A0b);
        res.y = coef1 * (A1a + A1b);
    }

    g_part[blockIdx.y][blockIdx.x * (RBLK / 2) + t] = res;
}

// ---------------- reduce: 4 threads per position, grid 140 -----------------
__global__ void __launch_bounds__(256)
reduce_kernel(float* __restrict__ out) {
    __shared__ float s_scale;
    __shared__ float s_SD[5];

    const int t    = threadIdx.x;
    const int lane = t & 31;
    const int wid  = t >> 5;

    if (wid == 0) {
        float x = g_pDCG[lane];                    // PBLK == 32
        #pragma unroll
        for (int o = 16; o > 0; o >>= 1)
            x += __shfl_down_sync(0xffffffffu, x, o);
        if (lane == 0) s_scale = __fdividef(1.0f, x);
    } else if (wid <= 5) {
        float x = g_pSD[lane][wid - 1];
        #pragma unroll
        for (int o = 16; o > 0; o >>= 1)
            x += __shfl_down_sync(0xffffffffu, x, o);
        if (lane == 0) s_SD[wid - 1] = x;
    }
    __syncthreads();

    const int kp  = blockIdx.x * 64 + (t >> 2);    // padded position
    const int sub = t & 3;                         // slice-group id

    float T1p = 0.0f;
    #pragma unroll
    for (int s = 0; s < NT / 4; s++)               // 17 full rounds
        T1p += ((const float*)g_part[sub + 4 * s])[kp];
    if (sub < 2)                                   // slices 68, 69
        T1p += ((const float*)g_part[68 + sub])[kp];

    T1p += __shfl_xor_sync(0xffffffffu, T1p, 1);
    T1p += __shfl_xor_sync(0xffffffffu, T1p, 2);
    const float T1 = T1p;

    if (sub != 0) return;
    const int idx = g_inv[kp];
    if (idx < 0) return;                           // padding slot

    const int pb1 = g_pbase[1], pb2 = g_pbase[2],
              pb3 = g_pbase[3], pb4 = g_pbase[4];
    const int v = (kp >= pb1) + (kp >= pb2) + (kp >= pb3) + (kp >= pb4);

    const float2 a = g_sed[kp];
    const float e = a.x;
    const float d = -a.y;
    const float g = (float)(1 << v);

    float T2 = 0.0f;
    #pragma unroll
    for (int c = 0; c < 4; c++) {
        if (c < v) {
            float nc = (float)(g_seg[c + 1] - g_seg[c]);
            T2 += ((float)(1 << c) - g) * (nc * d - s_SD[c]);
        }
    }

    out[idx] = s_scale * (e * T1 - T2);
}

extern "C" void kernel_launch(void* const* d_in, const int* in_sizes, int n_in,
                              void* d_out, int out_size) {
    const float* pred = (const float*)d_in[0];
    const float* tgt  = (const float*)d_in[1];
    float* out        = (float*)d_out;

    prep_count<<<PBLK, 256>>>(tgt);
    prep_scatter<<<PBLK, 256>>>(pred, tgt);
    dim3 grid(NRB, NT);
    pair_kernel<<<grid, PAIR_T>>>();
    reduce_kernel<<<NPAD / 64, 256>>>(out);
}

// round 16
// speedup vs baseline: 1.3067x; 1.0606x over previous
#include <cuda_runtime.h>

// LambdaRankLoss N=8192, 5 integer classes (0..4), SIGMA=1.
//
//   e = exp(p), g = 2^t, d = 1/log2(rank+1), rank = stable ascending-by-target.
//   lambda_i = scale * ( e_i * T1_i - T2_i ),  scale = 1/maxDCG
//   T1_i = sum_c (G_c - g_i) * sum_{j in c} (d_i - d_j) r_ij,  r = 1/(e_i+e_j)
//   T2_i = sum_{c < v_i} (G_c - g_i)(n_c d_i - SD_c)     [O(1), reduce]
//
// J-SPACE ONLY PADDING (pad e=1e18 finite): each 128-j tile single-class ->
// static 128-trip loop. ROWS iterate a COMPACT true-sorted array (8192) ->
// no pad-row work, 32x70=2240 blocks = single wave.
// RCP-MERGE: rp=rcp(s0*s1) serves both rows (1 MUFU / 2 pairs).

#define N      8192
#define K_DCG  512
#define NT     70            // 128-wide class-aligned j tiles
#define NPAD   (NT * 128)    // 8960
#define RBLK   256
#define NRB    (N / RBLK)    // 32  (true rows only)
#define PAIR_T 128
#define PBLK   32
#define PADE   1.0e18f

__device__ float2 g_sed[NPAD];       // padded-sorted (e, -decay) for J; pad=(1e18,0)
__device__ float2 g_sedT[N];         // TRUE-sorted (e, -decay) for rows
__device__ int    g_invT[N];         // true sorted pos -> original index
__device__ int    g_seg[8];          // TRUE class segment bounds
__device__ int    g_pbase[8];        // PADDED class segment bases
__device__ float  g_tGc[NT];         // per-tile class gain 2^c; 0 = all-pad tile
__device__ int    g_bcnt[PBLK][5];   // per-block class counts
__device__ float  g_pSD[PBLK][5];
__device__ float  g_pDCG[PBLK];
__device__ float2 g_part[NT][N / 2];

__device__ __forceinline__ float frcp(float x) {
    float r;
    asm("rcp.approx.f32 %0, %1;" : "=f"(r) : "f"(x));
    return r;
}

// ---------------- prep 1: clear j-padding + per-block class counts ---------
__global__ void __launch_bounds__(256)
prep_count(const float* __restrict__ tgt) {
    __shared__ int s_w[8][5];

    const int i    = blockIdx.x * 256 + threadIdx.x;
    const int lane = threadIdx.x & 31;
    const int wid  = threadIdx.x >> 5;

    const float2 padval = make_float2(PADE, 0.0f);
    g_sed[i] = padval;
    if (i < NPAD - N) g_sed[N + i] = padval;

    int v = (int)tgt[i];
    v = max(0, min(4, v));
    #pragma unroll
    for (int c = 0; c < 5; c++) {
        unsigned b = __ballot_sync(0xffffffffu, v == c);
        if (lane == c) s_w[wid][c] = __popc(b);
    }
    __syncthreads();

    if (threadIdx.x < 5) {
        int s = 0;
        #pragma unroll
        for (int w = 0; w < 8; w++) s += s_w[w][threadIdx.x];
        g_bcnt[blockIdx.x][threadIdx.x] = s;
    }
}

// ---------------- prep 2: local prefixes + dual scatter + SD/DCG + tables --
__global__ void __launch_bounds__(256)
prep_scatter(const float* __restrict__ pred, const float* __restrict__ tgt) {
    __shared__ int   s_w[8][5];
    __shared__ int   s_gexc[5];
    __shared__ int   s_tot[5];
    __shared__ float s_sd[8][5];
    __shared__ float s_dcg[8];

    const int i    = blockIdx.x * 256 + threadIdx.x;
    const int lane = threadIdx.x & 31;
    const int wid  = threadIdx.x >> 5;

    int v = (int)tgt[i];
    v = max(0, min(4, v));

    int intra = 0;
    #pragma unroll
    for (int c = 0; c < 5; c++) {
        unsigned b = __ballot_sync(0xffffffffu, v == c);
        if (v == c) intra = __popc(b & ((1u << lane) - 1u));
        if (lane == c) s_w[wid][c] = __popc(b);
    }

    if (wid == 0) {
        #pragma unroll
        for (int c = 0; c < 5; c++) {
            int own = g_bcnt[lane][c];
            int x = own;
            #pragma unroll
            for (int o = 1; o < 32; o <<= 1) {
                int y = __shfl_up_sync(0xffffffffu, x, o);
                if (lane >= o) x += y;
            }
            if (lane == blockIdx.x) s_gexc[c] = x - own;
            if (lane == 31)         s_tot[c]  = x;
        }
    }
    __syncthreads();

    int tot[5], baseT[5], pbase[6];
    {
        int run = 0, prun = 0;
        #pragma unroll
        for (int c = 0; c < 5; c++) {
            tot[c]   = s_tot[c];
            baseT[c] = run;
            pbase[c] = prun;
            run  += tot[c];
            prun += ((tot[c] + 127) >> 7) << 7;
        }
        pbase[5] = prun;
    }

    int wpre = 0;
    for (int w = 0; w < wid; w++) wpre += s_w[w][v];

    const int k  = baseT[v] + s_gexc[v] + wpre + intra;    // TRUE sorted pos
    const int kp = pbase[v] + (k - baseT[v]);              // PADDED pos (j-space)

    const float e = __expf(pred[i]);
    const float d = __fdividef(1.0f, log2f((float)k + 2.0f));
    const float2 ed = make_float2(e, -d);
    g_sed[kp]  = ed;                                       // j array (padded)
    g_sedT[k]  = ed;                                       // row array (compact)
    g_invT[k]  = i;

    float term = 0.0f;
    if (k >= N - K_DCG) {
        int r = N - k;                                     // descending rank
        term = (exp2f((float)v) - 1.0f) / log2f((float)r + 1.0f);
    }

    #pragma unroll
    for (int c = 0; c < 5; c++) {
        float x = (v == c) ? d : 0.0f;
        #pragma unroll
        for (int o = 16; o > 0; o >>= 1)
            x += __shfl_down_sync(0xffffffffu, x, o);
        if (lane == 0) s_sd[wid][c] = x;
    }
    {
        float x = term;
        #pragma unroll
        for (int o = 16; o > 0; o >>= 1)
            x += __shfl_down_sync(0xffffffffu, x, o);
        if (lane == 0) s_dcg[wid] = x;
    }
    __syncthreads();

    if (threadIdx.x < 5) {
        float s = 0.0f;
        #pragma unroll
        for (int w = 0; w < 8; w++) s += s_sd[w][threadIdx.x];
        g_pSD[blockIdx.x][threadIdx.x] = s;
    } else if (threadIdx.x == 5) {
        float s = 0.0f;
        #pragma unroll
        for (int w = 0; w < 8; w++) s += s_dcg[w];
        g_pDCG[blockIdx.x] = s;
    }

    if (blockIdx.x == 0 && threadIdx.x == 0) {
        #pragma unroll
        for (int c = 0; c < 5; c++) { g_seg[c] = baseT[c]; g_pbase[c] = pbase[c]; }
        g_seg[5]   = N;
        g_pbase[5] = pbase[5];
        for (int tl = 0; tl < NT; tl++) {
            int start = tl * 128;
            float gc = 0.0f;                      // 0 = all-pad tile (skipped)
            #pragma unroll
            for (int c = 0; c < 5; c++)
                if (start >= pbase[c] && start < pbase[c] +
                    (((tot[c] + 127) >> 7) << 7)) gc = (float)(1 << c);
            g_tGc[tl] = gc;
        }
    }
}

// ---------------- pairwise: grid (32, 70); compact rows, padded j ----------
__global__ void __launch_bounds__(PAIR_T)
pair_kernel() {
    const int t  = threadIdx.x;
    const int r0 = blockIdx.x * RBLK + 2 * t;     // TRUE sorted position
    const int r1 = r0 + 1;

    const int b1 = g_seg[1], b2 = g_seg[2], b3 = g_seg[3], b4 = g_seg[4];

    const float2 a0 = g_sedT[r0];
    const float2 a1 = g_sedT[r1];
    const float e0 = a0.x, d0 = -a0.y;
    const float e1 = a1.x, d1 = -a1.y;
    const float gi0 = (float)(1 << ((r0 >= b1) + (r0 >= b2) + (r0 >= b3) + (r0 >= b4)));
    const float gi1 = (float)(1 << ((r1 >= b1) + (r1 >= b2) + (r1 >= b3) + (r1 >= b4)));

    const float Gc    = g_tGc[blockIdx.y];
    const float coef0 = Gc - gi0;
    const float coef1 = Gc - gi1;

    float2 res = make_float2(0.0f, 0.0f);

    bool skip = (Gc == 0.0f) ||
                __all_sync(0xffffffffu, (coef0 == 0.0f) && (coef1 == 0.0f));
    if (!skip) {
        const float4* __restrict__ p = (const float4*)(g_sed + blockIdx.y * 128);

        float A0a = 0.f, A0b = 0.f, A1a = 0.f, A1b = 0.f;

        #pragma unroll 8
        for (int j = 0; j < 64; j++) {
            const float4 w = __ldg(p + j);         // (e_a, nd_a, e_b, nd_b)
            {
                float s0  = e0 + w.x;
                float s1  = e1 + w.x;
                float rp  = frcp(s0 * s1);          // one MUFU for both rows
                float dd0 = d0 + w.y;
                float dd1 = d1 + w.y;
                A0a = fmaf(dd0, rp * s1, A0a);
                A1a = fmaf(dd1, rp * s0, A1a);
            }
            {
                float s0  = e0 + w.z;
                float s1  = e1 + w.z;
                float rp  = frcp(s0 * s1);
                float dd0 = d0 + w.w;
                float dd1 = d1 + w.w;
                A0b = fmaf(dd0, rp * s1, A0b);
                A1b = fmaf(dd1, rp * s0, A1b);
            }
        }
        res.x = coef0 * (A0a + A0b);
        res.y = coef1 * (A1a + A1b);
    }

    g_part[blockIdx.y][blockIdx.x * (RBLK / 2) + t] = res;
}

// ---------------- reduce: 4 threads per position, grid 128 -----------------
__global__ void __launch_bounds__(256)
reduce_kernel(float* __restrict__ out) {
    __shared__ float s_scale;
    __shared__ float s_SD[5];

    const int t    = threadIdx.x;
    const int lane = t & 31;
    const int wid  = t >> 5;

    if (wid == 0) {
        float x = g_pDCG[lane];                    // PBLK == 32
        #pragma unroll
        for (int o = 16; o > 0; o >>= 1)
            x += __shfl_down_sync(0xffffffffu, x, o);
        if (lane == 0) s_scale = __fdividef(1.0f, x);
    } else if (wid <= 5) {
        float x = g_pSD[lane][wid - 1];
        #pragma unroll
        for (int o = 16; o > 0; o >>= 1)
            x += __shfl_down_sync(0xffffffffu, x, o);
        if (lane == 0) s_SD[wid - 1] = x;
    }
    __syncthreads();

    const int k   = blockIdx.x * 64 + (t >> 2);    // TRUE sorted position
    const int sub = t & 3;

    float T1p = 0.0f;
    #pragma unroll
    for (int s = 0; s < NT / 4; s++)               // 17 full rounds
        T1p += ((const float*)g_part[sub + 4 * s])[k];
    if (sub < 2)                                   // slices 68, 69
        T1p += ((const float*)g_part[68 + sub])[k];

    T1p += __shfl_xor_sync(0xffffffffu, T1p, 1);
    T1p += __shfl_xor_sync(0xffffffffu, T1p, 2);
    const float T1 = T1p;

    if (sub != 0) return;

    const int b1 = g_seg[1], b2 = g_seg[2], b3 = g_seg[3], b4 = g_seg[4];
    const int v = (k >= b1) + (k >= b2) + (k >= b3) + (k >= b4);

    const float2 a = g_sedT[k];
    const float e = a.x;
    const float d = -a.y;
    const float g = (float)(1 << v);

    float T2 = 0.0f;
    #pragma unroll
    for (int c = 0; c < 4; c++) {
        if (c < v) {
            float nc = (float)(g_seg[c + 1] - g_seg[c]);
            T2 += ((float)(1 << c) - g) * (nc * d - s_SD[c]);
        }
    }

    out[g_invT[k]] = s_scale * (e * T1 - T2);
}

extern "C" void kernel_launch(void* const* d_in, const int* in_sizes, int n_in,
                              void* d_out, int out_size) {
    const float* pred = (const float*)d_in[0];
    const float* tgt  = (const float*)d_in[1];
    float* out        = (float*)d_out;

    prep_count<<<PBLK, 256>>>(tgt);
    prep_scatter<<<PBLK, 256>>>(pred, tgt);
    dim3 grid(NRB, NT);
    pair_kernel<<<grid, PAIR_T>>>();
    reduce_kernel<<<N / 64, 256>>>(out);
}

// round 17
// speedup vs baseline: 1.3080x; 1.0010x over previous
#include <cuda_runtime.h>

// LambdaRankLoss N=8192, 5 integer classes (0..4), SIGMA=1.
//
//   e = exp(p), g = 2^t, d = 1/log2(rank+1), rank = stable ascending-by-target.
//   lambda_i = scale * ( e_i * T1_i - T2_i ),  scale = 1/maxDCG
//   T1_i = sum_c (G_c - g_i) * sum_{j in c} (d_i - d_j)/(e_i + e_j)
//   T2_i = sum_{c < v_i} (G_c - g_i)(n_c d_i - SD_c)     [O(1), reduce]
//
// T-SUM EXPANSION (per row-pair (0,1), rp = 1/((e0+ej)(e1+ej))):
//   pp  = fmaf(ej, ej+E, P),  E = e0+e1, P = e0*e1      [no s0/s1 needed!]
//   sum_j (d0+ndj)/(e0+ej) = d0*e1*T1 + d0*Tu + e1*Tw + Tuw
//   T1 = sum rp, Tu = sum ej*rp, Tw = sum ndj*rp, Tuw = sum (ej*ndj)*rp
// -> 6 fma-pipe + 1 MUFU per TWO pairs (3 fma/pair, was 4.5).
// 4 rows/thread share each j-load. J padded to 128-aligned class tiles
// (pad e=1e18, nd=end=0 -> contribution ~1e-18). Rows iterate compact array.

#define N      8192
#define K_DCG  512
#define NT     70            // 128-wide class-aligned j tiles
#define NPAD   (NT * 128)    // 8960
#define RBLK   512           // rows per block (4 per thread)
#define NRB    (N / RBLK)    // 16
#define PAIR_T 128
#define PBLK   32
#define PADE   1.0e18f

__device__ float4 g_sed4[NPAD];      // padded-sorted (e, -d, -e*d, 0) for J
__device__ float2 g_sedT[N];         // TRUE-sorted (e, -d) for rows
__device__ int    g_invT[N];         // true sorted pos -> original index
__device__ int    g_seg[8];          // TRUE class segment bounds
__device__ int    g_pbase[8];        // PADDED class segment bases
__device__ float  g_tGc[NT];         // per-tile class gain 2^c; 0 = all-pad tile
__device__ int    g_bcnt[PBLK][5];   // per-block class counts
__device__ float  g_pSD[PBLK][5];
__device__ float  g_pDCG[PBLK];
__device__ float  g_part[NT][N];

__device__ __forceinline__ float frcp(float x) {
    float r;
    asm("rcp.approx.f32 %0, %1;" : "=f"(r) : "f"(x));
    return r;
}

// ---------------- prep 1: clear j-padding + per-block class counts ---------
__global__ void __launch_bounds__(256)
prep_count(const float* __restrict__ tgt) {
    __shared__ int s_w[8][5];

    const int i    = blockIdx.x * 256 + threadIdx.x;
    const int lane = threadIdx.x & 31;
    const int wid  = threadIdx.x >> 5;

    const float4 padval = make_float4(PADE, 0.0f, 0.0f, 0.0f);
    g_sed4[i] = padval;
    if (i < NPAD - N) g_sed4[N + i] = padval;

    int v = (int)tgt[i];
    v = max(0, min(4, v));
    #pragma unroll
    for (int c = 0; c < 5; c++) {
        unsigned b = __ballot_sync(0xffffffffu, v == c);
        if (lane == c) s_w[wid][c] = __popc(b);
    }
    __syncthreads();

    if (threadIdx.x < 5) {
        int s = 0;
        #pragma unroll
        for (int w = 0; w < 8; w++) s += s_w[w][threadIdx.x];
        g_bcnt[blockIdx.x][threadIdx.x] = s;
    }
}

// ---------------- prep 2: local prefixes + dual scatter + SD/DCG + tables --
__global__ void __launch_bounds__(256)
prep_scatter(const float* __restrict__ pred, const float* __restrict__ tgt) {
    __shared__ int   s_w[8][5];
    __shared__ int   s_gexc[5];
    __shared__ int   s_tot[5];
    __shared__ float s_sd[8][5];
    __shared__ float s_dcg[8];

    const int i    = blockIdx.x * 256 + threadIdx.x;
    const int lane = threadIdx.x & 31;
    const int wid  = threadIdx.x >> 5;

    int v = (int)tgt[i];
    v = max(0, min(4, v));

    int intra = 0;
    #pragma unroll
    for (int c = 0; c < 5; c++) {
        unsigned b = __ballot_sync(0xffffffffu, v == c);
        if (v == c) intra = __popc(b & ((1u << lane) - 1u));
        if (lane == c) s_w[wid][c] = __popc(b);
    }

    if (wid == 0) {
        #pragma unroll
        for (int c = 0; c < 5; c++) {
            int own = g_bcnt[lane][c];
            int x = own;
            #pragma unroll
            for (int o = 1; o < 32; o <<= 1) {
                int y = __shfl_up_sync(0xffffffffu, x, o);
                if (lane >= o) x += y;
            }
            if (lane == blockIdx.x) s_gexc[c] = x - own;
            if (lane == 31)         s_tot[c]  = x;
        }
    }
    __syncthreads();

    int tot[5], baseT[5], pbase[6];
    {
        int run = 0, prun = 0;
        #pragma unroll
        for (int c = 0; c < 5; c++) {
            tot[c]   = s_tot[c];
            baseT[c] = run;
            pbase[c] = prun;
            run  += tot[c];
            prun += ((tot[c] + 127) >> 7) << 7;
        }
        pbase[5] = prun;
    }

    int wpre = 0;
    for (int w = 0; w < wid; w++) wpre += s_w[w][v];

    const int k  = baseT[v] + s_gexc[v] + wpre + intra;    // TRUE sorted pos
    const int kp = pbase[v] + (k - baseT[v]);              // PADDED pos (j-space)

    const float e = __expf(pred[i]);
    const float d = __fdividef(1.0f, log2f((float)k + 2.0f));
    g_sed4[kp] = make_float4(e, -d, -e * d, 0.0f);
    g_sedT[k]  = make_float2(e, -d);
    g_invT[k]  = i;

    float term = 0.0f;
    if (k >= N - K_DCG) {
        int r = N - k;                                     // descending rank
        term = (exp2f((float)v) - 1.0f) / log2f((float)r + 1.0f);
    }

    #pragma unroll
    for (int c = 0; c < 5; c++) {
        float x = (v == c) ? d : 0.0f;
        #pragma unroll
        for (int o = 16; o > 0; o >>= 1)
            x += __shfl_down_sync(0xffffffffu, x, o);
        if (lane == 0) s_sd[wid][c] = x;
    }
    {
        float x = term;
        #pragma unroll
        for (int o = 16; o > 0; o >>= 1)
            x += __shfl_down_sync(0xffffffffu, x, o);
        if (lane == 0) s_dcg[wid] = x;
    }
    __syncthreads();

    if (threadIdx.x < 5) {
        float s = 0.0f;
        #pragma unroll
        for (int w = 0; w < 8; w++) s += s_sd[w][threadIdx.x];
        g_pSD[blockIdx.x][threadIdx.x] = s;
    } else if (threadIdx.x == 5) {
        float s = 0.0f;
        #pragma unroll
        for (int w = 0; w < 8; w++) s += s_dcg[w];
        g_pDCG[blockIdx.x] = s;
    }

    if (blockIdx.x == 0 && threadIdx.x == 0) {
        #pragma unroll
        for (int c = 0; c < 5; c++) { g_seg[c] = baseT[c]; g_pbase[c] = pbase[c]; }
        g_seg[5]   = N;
        g_pbase[5] = pbase[5];
        for (int tl = 0; tl < NT; tl++) {
            int start = tl * 128;
            float gc = 0.0f;                      // 0 = all-pad tile (skipped)
            #pragma unroll
            for (int c = 0; c < 5; c++)
                if (start >= pbase[c] && start < pbase[c] +
                    (((tot[c] + 127) >> 7) << 7)) gc = (float)(1 << c);
            g_tGc[tl] = gc;
        }
    }
}

// ---------------- pairwise: grid (16, 70); 4 rows/thread, T-sum form -------
__global__ void __launch_bounds__(PAIR_T)
pair_kernel() {
    const int t  = threadIdx.x;
    const int r0 = blockIdx.x * RBLK + 4 * t;     // TRUE sorted position

    const int b1 = g_seg[1], b2 = g_seg[2], b3 = g_seg[3], b4 = g_seg[4];

    // rows r0..r3 as two float4 loads
    const float4* __restrict__ pT = (const float4*)g_sedT;
    const float4 ra = pT[2 * (blockIdx.x * (RBLK / 4) + t)];
    const float4 rb = pT[2 * (blockIdx.x * (RBLK / 4) + t) + 1];
    const float e0 = ra.x, d0 = -ra.y;
    const float e1 = ra.z, d1 = -ra.w;
    const float e2 = rb.x, d2 = -rb.y;
    const float e3 = rb.z, d3 = -rb.w;

    float gi[4];
    #pragma unroll
    for (int h = 0; h < 4; h++) {
        int r = r0 + h;
        gi[h] = (float)(1 << ((r >= b1) + (r >= b2) + (r >= b3) + (r >= b4)));
    }

    const float Gc = g_tGc[blockIdx.y];
    const float coef0 = Gc - gi[0], coef1 = Gc - gi[1];
    const float coef2 = Gc - gi[2], coef3 = Gc - gi[3];

    float4 res = make_float4(0.0f, 0.0f, 0.0f, 0.0f);

    bool skip = (Gc == 0.0f) ||
                __all_sync(0xffffffffu,
                           (coef0 == 0.0f) && (coef1 == 0.0f) &&
                           (coef2 == 0.0f) && (coef3 == 0.0f));
    if (!skip) {
        // merged-rcp constants per row pair
        const float E01 = e0 + e1, P01 = e0 * e1;
        const float E23 = e2 + e3, P23 = e2 * e3;
        const float d0e1 = d0 * e1, d1e0 = d1 * e0;
        const float d2e3 = d2 * e3, d3e2 = d3 * e2;

        const float4* __restrict__ p = g_sed4 + blockIdx.y * 128;

        float T1a = 0.f, Tua = 0.f, Twa = 0.f, Tva = 0.f;
        float T1b = 0.f, Tub = 0.f, Twb = 0.f, Tvb = 0.f;

        #pragma unroll 8
        for (int j = 0; j < 128; j++) {
            const float4 w = __ldg(p + j);         // (ej, ndj, ej*ndj, 0)
            // row pair (0,1)
            float ppa = fmaf(w.x, w.x + E01, P01);
            float rpa = frcp(ppa);
            T1a += rpa;
            Tua = fmaf(w.x, rpa, Tua);
            Twa = fmaf(w.y, rpa, Twa);
            Tva = fmaf(w.z, rpa, Tva);
            // row pair (2,3)
            float ppb = fmaf(w.x, w.x + E23, P23);
            float rpb = frcp(ppb);
            T1b += rpb;
            Tub = fmaf(w.x, rpb, Tub);
            Twb = fmaf(w.y, rpb, Twb);
            Tvb = fmaf(w.z, rpb, Tvb);
        }

        // A_h = sum_j (d_h + ndj)/(e_h + ej)
        float A0 = fmaf(d0e1, T1a, fmaf(d0, Tua, fmaf(e1, Twa, Tva)));
        float A1 = fmaf(d1e0, T1a, fmaf(d1, Tua, fmaf(e0, Twa, Tva)));
        float A2 = fmaf(d2e3, T1b, fmaf(d2, Tub, fmaf(e3, Twb, Tvb)));
        float A3 = fmaf(d3e2, T1b, fmaf(d3, Tub, fmaf(e2, Twb, Tvb)));

        res.x = coef0 * A0;
        res.y = coef1 * A1;
        res.z = coef2 * A2;
        res.w = coef3 * A3;
    }

    *reinterpret_cast<float4*>(&g_part[blockIdx.y][blockIdx.x * RBLK + 4 * t]) = res;
}

// ---------------- reduce: 4 threads per position, grid 128 -----------------
__global__ void __launch_bounds__(256)
reduce_kernel(float* __restrict__ out) {
    __shared__ float s_scale;
    __shared__ float s_SD[5];

    const int t    = threadIdx.x;
    const int lane = t & 31;
    const int wid  = t >> 5;

    if (wid == 0) {
        float x = g_pDCG[lane];                    // PBLK == 32
        #pragma unroll
        for (int o = 16; o > 0; o >>= 1)
            x += __shfl_down_sync(0xffffffffu, x, o);
        if (lane == 0) s_scale = __fdividef(1.0f, x);
    } else if (wid <= 5) {
        float x = g_pSD[lane][wid - 1];
        #pragma unroll
        for (int o = 16; o > 0; o >>= 1)
            x += __shfl_down_sync(0xffffffffu, x, o);
        if (lane == 0) s_SD[wid - 1] = x;
    }
    __syncthreads();

    const int k   = blockIdx.x * 64 + (t >> 2);    // TRUE sorted position
    const int sub = t & 3;

    float T1p = 0.0f;
    #pragma unroll
    for (int s = 0; s < NT / 4; s++)               // 17 full rounds
        T1p += g_part[sub + 4 * s][k];
    if (sub < 2)                                   // slices 68, 69
        T1p += g_part[68 + sub][k];

    T1p += __shfl_xor_sync(0xffffffffu, T1p, 1);
    T1p += __shfl_xor_sync(0xffffffffu, T1p, 2);
    const float T1 = T1p;

    if (sub != 0) return;

    const int b1 = g_seg[1], b2 = g_seg[2], b3 = g_seg[3], b4 = g_seg[4];
    const int v = (k >= b1) + (k >= b2) + (k >= b3) + (k >= b4);

    const float2 a = g_sedT[k];
    const float e = a.x;
    const float d = -a.y;
    const float g = (float)(1 << v);

    float T2 = 0.0f;
    #pragma unroll
    for (int c = 0; c < 4; c++) {
        if (c < v) {
            float nc = (float)(g_seg[c + 1] - g_seg[c]);
            T2 += ((float)(1 << c) - g) * (nc * d - s_SD[c]);
        }
    }

    out[g_invT[k]] = s_scale * (e * T1 - T2);
}

extern "C" void kernel_launch(void* const* d_in, const int* in_sizes, int n_in,
                              void* d_out, int out_size) {
    const float* pred = (const float*)d_in[0];
    const float* tgt  = (const float*)d_in[1];
    float* out        = (float*)d_out;

    prep_count<<<PBLK, 256>>>(tgt);
    prep_scatter<<<PBLK, 256>>>(pred, tgt);
    dim3 grid(NRB, NT);
    pair_kernel<<<grid, PAIR_T>>>();
    reduce_kernel<<<N / 64, 256>>>(out);
}